// round 2
// baseline (speedup 1.0000x reference)
#include <cuda_runtime.h>
#include <math.h>

#define NN 50000
#define NE 800000
#define DD 128
#define NG 16

#define NEG_INF_BITS 0xFF800000u

// Scratch (no cudaMalloc allowed). Declared as float4 for guaranteed 16B alignment.
__device__ float4 g_bufA4[NN * DD / 4];
__device__ float4 g_bufB4[NN * DD / 4];
__device__ float4 g_agg4[NN * DD / 4];
__device__ float g_xg[NG * DD];
__device__ int g_i64; // 1 if index inputs are int64, 0 if int32

__device__ __forceinline__ const float* sel_in(int sel, const float* x, const float* dout) {
    return sel == 0 ? x : sel == 1 ? (const float*)g_bufA4 : sel == 2 ? (const float*)g_bufB4 : dout;
}
__device__ __forceinline__ float* sel_out(int sel, float* dout) {
    return sel == 1 ? (float*)g_bufA4 : sel == 2 ? (float*)g_bufB4 : dout;
}

// Exact float atomic max via integer-ordering trick (slots init'd to -inf bits).
__device__ __forceinline__ void atomicMaxF(float* a, float v) {
    if (v >= 0.f) atomicMax((int*)a, __float_as_int(v));
    else          atomicMin((unsigned int*)a, __float_as_uint(v));
}

// fast-math-safe -inf -> 0
__device__ __forceinline__ float fixneg(float v) {
    return (__float_as_uint(v) == NEG_INF_BITS) ? 0.f : v;
}

// ---------------- dtype detection ----------------
// int64 little-endian values < 2^31 look like [v,0,v,0,...] in the int32 view.
// Reading the int32 view is in-bounds under either true dtype.
__global__ void k_detect(const int* __restrict__ ei32) {
    int mode = 1;
    for (int i = 0; i < 64; ++i) {
        if (ei32[2 * i + 1] != 0) { mode = 0; break; }
    }
    g_i64 = mode;
}

// ---------------- init kernels ----------------
__global__ void k_init_agg() {
    unsigned int i = blockIdx.x * blockDim.x + threadIdx.x;
    if (i < (NN * DD) / 4) {
        uint4 v = make_uint4(NEG_INF_BITS, NEG_INF_BITS, NEG_INF_BITS, NEG_INF_BITS);
        ((uint4*)g_agg4)[i] = v;
    }
}

__global__ void k_init_xg() {
    unsigned int i = blockIdx.x * blockDim.x + threadIdx.x;
    if (i < NG * DD) ((unsigned int*)g_xg)[i] = NEG_INF_BITS;
}

// ---------------- edge scatter-max ----------------
// 32 threads cover one edge's 128 dims (float4 each).
__global__ void k_scatter(int insel, const float* __restrict__ x, const float* __restrict__ doutc,
                          const int* __restrict__ ei32) {
    const float* h = sel_in(insel, x, doutc);
    long long idx = (long long)blockIdx.x * blockDim.x + threadIdx.x;
    if (idx >= (long long)NE * 32) return;
    int e = (int)(idx >> 5);
    int q = (int)(idx & 31);
    int s, d;
    if (g_i64) { s = ei32[2 * e]; d = ei32[2 * (NE + e)]; }
    else       { s = ei32[e];     d = ei32[NE + e]; }
    const float4 v = *(const float4*)(h + (size_t)s * DD + q * 4);
    float* ap = (float*)g_agg4 + (size_t)d * DD + q * 4;
    atomicMaxF(ap + 0, v.x);
    atomicMaxF(ap + 1, v.y);
    atomicMaxF(ap + 2, v.z);
    atomicMaxF(ap + 3, v.w);
}

// ---------------- fused concat-GEMM + bias + leaky + residual ----------------
// C[m,n] = leaky( h[m,:]@W[0:128,n] + fix(agg[m,:])@W[128:256,n] + b[n] ) (+ h[m,n] if skip)
// Block: 64 rows x 128 cols, thread tile 8x4, BK=16.
__global__ void k_gemm(int insel, int outsel, const float* __restrict__ x, float* __restrict__ dout,
                       const float* __restrict__ w, const float* __restrict__ b, int addskip) {
    const float* h = sel_in(insel, x, dout);
    float* out = sel_out(outsel, dout);

    __shared__ float As[16][64];
    __shared__ float Ws[16][128];

    const int tid = threadIdx.x;
    const int tx = tid & 31;
    const int ty = tid >> 5;
    const int m0 = blockIdx.x * 64;

    const int arow = tid >> 2;       // 0..63
    const int acg = (tid & 3) * 4;   // 0,4,8,12

    float acc[8][4];
#pragma unroll
    for (int i = 0; i < 8; ++i)
#pragma unroll
        for (int j = 0; j < 4; ++j) acc[i][j] = 0.f;

    for (int kt = 0; kt < 16; ++kt) {
        const float* A = (kt < 8) ? h : (const float*)g_agg4;
        const int kloc = (kt & 7) * 16 + acg;

        float4 av = make_float4(0.f, 0.f, 0.f, 0.f);
        const int gr = m0 + arow;
        if (gr < NN) av = *(const float4*)(A + (size_t)gr * DD + kloc);
        if (kt >= 8) {  // empty segments: -inf -> 0 (bit compare, fast-math safe)
            av.x = fixneg(av.x); av.y = fixneg(av.y);
            av.z = fixneg(av.z); av.w = fixneg(av.w);
        }
        As[acg + 0][arow] = av.x;
        As[acg + 1][arow] = av.y;
        As[acg + 2][arow] = av.z;
        As[acg + 3][arow] = av.w;

#pragma unroll
        for (int t = 0; t < 2; ++t) {
            int i = tid + t * 256;
            int r = i >> 5;
            int c = (i & 31) << 2;
            *(float4*)&Ws[r][c] = *(const float4*)(w + (size_t)(kt * 16 + r) * DD + c);
        }
        __syncthreads();

#pragma unroll
        for (int kk = 0; kk < 16; ++kk) {
            float a[8];
#pragma unroll
            for (int i = 0; i < 8; ++i) a[i] = As[kk][ty * 8 + i];
            float4 wv = *(const float4*)&Ws[kk][tx * 4];
#pragma unroll
            for (int i = 0; i < 8; ++i) {
                acc[i][0] = fmaf(a[i], wv.x, acc[i][0]);
                acc[i][1] = fmaf(a[i], wv.y, acc[i][1]);
                acc[i][2] = fmaf(a[i], wv.z, acc[i][2]);
                acc[i][3] = fmaf(a[i], wv.w, acc[i][3]);
            }
        }
        __syncthreads();
    }

    const float4 bias = *(const float4*)(b + tx * 4);
#pragma unroll
    for (int i = 0; i < 8; ++i) {
        int gr = m0 + ty * 8 + i;
        if (gr < NN) {
            float4 v;
            v.x = acc[i][0] + bias.x;
            v.y = acc[i][1] + bias.y;
            v.z = acc[i][2] + bias.z;
            v.w = acc[i][3] + bias.w;
            v.x = v.x > 0.f ? v.x : 0.01f * v.x;
            v.y = v.y > 0.f ? v.y : 0.01f * v.y;
            v.z = v.z > 0.f ? v.z : 0.01f * v.z;
            v.w = v.w > 0.f ? v.w : 0.01f * v.w;
            if (addskip) {
                float4 hv = *(const float4*)(h + (size_t)gr * DD + tx * 4);
                v.x += hv.x; v.y += hv.y; v.z += hv.z; v.w += hv.w;
            }
            *(float4*)(out + (size_t)gr * DD + tx * 4) = v;
        }
    }
}

// ---------------- global pool ----------------
__device__ __forceinline__ int batch_at(const int* b32, int i) {
    return g_i64 ? b32[2 * i] : b32[i];
}

__device__ __forceinline__ int lower_bound_b(const int* b32, int n, int v) {
    int lo = 0, hi = n;
    while (lo < hi) {
        int mid = (lo + hi) >> 1;
        if (batch_at(b32, mid) < v) lo = mid + 1;
        else hi = mid;
    }
    return lo;
}

__global__ void k_segmax(const float* __restrict__ h, const int* __restrict__ batch32) {
    const int g = blockIdx.x;
    const int chunk = blockIdx.y;
    const int d = threadIdx.x;
    int start = lower_bound_b(batch32, NN, g);
    int end = lower_bound_b(batch32, NN, g + 1);
    int len = end - start;
    if (len <= 0) return;
    int per = (len + gridDim.y - 1) / gridDim.y;
    int s = start + chunk * per;
    int e = s + per;
    if (e > end) e = end;
    if (s >= e) return;
    float m = __uint_as_float(NEG_INF_BITS);
    for (int r = s; r < e; ++r) m = fmaxf(m, h[(size_t)r * DD + d]);
    atomicMaxF(&g_xg[g * DD + d], m);
}

// xg_out = leaky( fix(xg) @ wg[0:128] + bg )  (concat partner is zeros)
__global__ void k_combine(float* __restrict__ dout, const float* __restrict__ wg,
                          const float* __restrict__ bg, int out_size) {
    const int g = blockIdx.x;
    const int n = threadIdx.x;
    float acc = bg[n];
    for (int k = 0; k < DD; ++k) {
        float xv = fixneg(g_xg[g * DD + k]);
        acc = fmaf(xv, wg[(size_t)k * DD + n], acc);
    }
    acc = acc > 0.f ? acc : 0.01f * acc;
    long long oi = (long long)NN * DD + g * DD + n;
    if (oi < (long long)out_size) dout[oi] = acc;
}

// ---------------- launch ----------------
extern "C" void kernel_launch(void* const* d_in, const int* in_sizes, int n_in,
                              void* d_out, int out_size) {
    const float* x = (const float*)d_in[0];
    const int* ei32 = (const int*)d_in[1];
    const int* batch32 = (const int*)d_in[2];
    const int wb = n_in - 10;  // last 10 inputs: w0,b0,w1,b1,w2,b2,w3,b3,wg,bg
    float* dout = (float*)d_out;

    k_detect<<<1, 1>>>(ei32);

    int insel = 0;
    for (int s = 0; s < 4; ++s) {
        int outsel = (s == 3) ? 3 : ((s % 2 == 0) ? 1 : 2);
        k_init_agg<<<(NN * DD / 4 + 255) / 256, 256>>>();
        k_scatter<<<(int)(((long long)NE * 32 + 255) / 256), 256>>>(insel, x, dout, ei32);
        k_gemm<<<(NN + 63) / 64, 256>>>(insel, outsel, x, dout,
                                        (const float*)d_in[wb + 2 * s],
                                        (const float*)d_in[wb + 2 * s + 1],
                                        s > 0 ? 1 : 0);
        insel = outsel;
    }

    k_init_xg<<<8, 256>>>();
    dim3 gsg(NG, 32);
    k_segmax<<<gsg, 128>>>(dout, batch32);
    k_combine<<<NG, 128>>>(dout, (const float*)d_in[wb + 8], (const float*)d_in[wb + 9], out_size);
}

// round 3
// speedup vs baseline: 2.6944x; 2.6944x over previous
#include <cuda_runtime.h>
#include <math.h>

#define NN 50000
#define NE 800000
#define DD 128
#define NG 16

#define NEG_INF_BITS 0xFF800000u

// Scratch (no cudaMalloc allowed). float4 for guaranteed 16B alignment.
__device__ float4 g_bufA4[NN * DD / 4];
__device__ float4 g_bufB4[NN * DD / 4];
__device__ float4 g_agg4[NN * DD / 4];
__device__ float g_xg[NG * DD];
__device__ int g_i64;            // 1 if index inputs are int64, 0 if int32
// CSR (dst-sorted adjacency), built once per launch
__device__ int g_deg[NN];
__device__ int g_off[NN + 1];
__device__ int g_cur[NN];
__device__ int g_csr[NE];

__device__ __forceinline__ const float* sel_in(int sel, const float* x, const float* dout) {
    return sel == 0 ? x : sel == 1 ? (const float*)g_bufA4 : sel == 2 ? (const float*)g_bufB4 : dout;
}
__device__ __forceinline__ float* sel_out(int sel, float* dout) {
    return sel == 1 ? (float*)g_bufA4 : sel == 2 ? (float*)g_bufB4 : dout;
}

__device__ __forceinline__ void atomicMaxF(float* a, float v) {
    if (v >= 0.f) atomicMax((int*)a, __float_as_int(v));
    else          atomicMin((unsigned int*)a, __float_as_uint(v));
}

__device__ __forceinline__ float fixneg(float v) {
    return (__float_as_uint(v) == NEG_INF_BITS) ? 0.f : v;
}

// ---------------- dtype detection ----------------
__global__ void k_detect(const int* __restrict__ ei32) {
    int mode = 1;
    for (int i = 0; i < 64; ++i) {
        if (ei32[2 * i + 1] != 0) { mode = 0; break; }
    }
    g_i64 = mode;
}

__device__ __forceinline__ int idx_at(const int* p32, int i) {
    return g_i64 ? p32[2 * i] : p32[i];
}

// ---------------- CSR build (once per launch) ----------------
__global__ void k_zero_deg() {
    int i = blockIdx.x * blockDim.x + threadIdx.x;
    if (i < NN) g_deg[i] = 0;
}

__global__ void k_count(const int* __restrict__ ei32) {
    int e = blockIdx.x * blockDim.x + threadIdx.x;
    if (e < NE) atomicAdd(&g_deg[idx_at(ei32, NE + e)], 1);
}

__global__ void k_scan() {  // single block, 1024 threads
    __shared__ int ps[1024];
    const int t = threadIdx.x;
    const int C = (NN + 1023) / 1024;
    const int base = t * C;
    int sum = 0;
    for (int i = 0; i < C; ++i) {
        int idx = base + i;
        if (idx < NN) sum += g_deg[idx];
    }
    ps[t] = sum;
    __syncthreads();
    for (int off = 1; off < 1024; off <<= 1) {
        int v = (t >= off) ? ps[t - off] : 0;
        __syncthreads();
        ps[t] += v;
        __syncthreads();
    }
    int run = (t > 0) ? ps[t - 1] : 0;
    for (int i = 0; i < C; ++i) {
        int idx = base + i;
        if (idx < NN) {
            g_off[idx] = run;
            g_cur[idx] = run;
            run += g_deg[idx];
        }
    }
    if (t == 1023) g_off[NN] = NE;
}

__global__ void k_fill(const int* __restrict__ ei32) {
    int e = blockIdx.x * blockDim.x + threadIdx.x;
    if (e < NE) {
        int d = idx_at(ei32, NE + e);
        int s = idx_at(ei32, e);
        int pos = atomicAdd(&g_cur[d], 1);
        g_csr[pos] = s;
    }
}

// ---------------- aggregation: warp-per-node gather-max ----------------
// 8 warps per block. Each warp: node n; 32 lanes x float4 = 128 dims.
__global__ void k_agg(int insel, const float* __restrict__ x, const float* __restrict__ doutc) {
    const float* h = sel_in(insel, x, doutc);
    const int warp = (blockIdx.x * blockDim.x + threadIdx.x) >> 5;
    const int lane = threadIdx.x & 31;
    if (warp >= NN) return;
    const int e0 = g_off[warp];
    const int e1 = g_off[warp + 1];
    float4 m = make_float4(0.f, 0.f, 0.f, 0.f);
    if (e1 > e0) {
        const float ni = __uint_as_float(NEG_INF_BITS);
        m = make_float4(ni, ni, ni, ni);
        int e = e0;
        // 2-wide unroll for MLP
        for (; e + 1 < e1; e += 2) {
            int s0 = g_csr[e];
            int s1 = g_csr[e + 1];
            float4 v0 = ((const float4*)h)[(size_t)s0 * 32 + lane];
            float4 v1 = ((const float4*)h)[(size_t)s1 * 32 + lane];
            m.x = fmaxf(m.x, v0.x); m.y = fmaxf(m.y, v0.y);
            m.z = fmaxf(m.z, v0.z); m.w = fmaxf(m.w, v0.w);
            m.x = fmaxf(m.x, v1.x); m.y = fmaxf(m.y, v1.y);
            m.z = fmaxf(m.z, v1.z); m.w = fmaxf(m.w, v1.w);
        }
        if (e < e1) {
            int s0 = g_csr[e];
            float4 v0 = ((const float4*)h)[(size_t)s0 * 32 + lane];
            m.x = fmaxf(m.x, v0.x); m.y = fmaxf(m.y, v0.y);
            m.z = fmaxf(m.z, v0.z); m.w = fmaxf(m.w, v0.w);
        }
    }
    g_agg4[(size_t)warp * 32 + lane] = m;
}

// ---------------- fused concat-GEMM + bias + leaky + residual ----------------
__global__ void k_gemm(int insel, int outsel, const float* __restrict__ x, float* __restrict__ dout,
                       const float* __restrict__ w, const float* __restrict__ b, int addskip) {
    const float* h = sel_in(insel, x, dout);
    float* out = sel_out(outsel, dout);

    __shared__ float As[16][64];
    __shared__ float Ws[16][128];

    const int tid = threadIdx.x;
    const int tx = tid & 31;
    const int ty = tid >> 5;
    const int m0 = blockIdx.x * 64;

    const int arow = tid >> 2;
    const int acg = (tid & 3) * 4;

    float acc[8][4];
#pragma unroll
    for (int i = 0; i < 8; ++i)
#pragma unroll
        for (int j = 0; j < 4; ++j) acc[i][j] = 0.f;

    for (int kt = 0; kt < 16; ++kt) {
        const float* A = (kt < 8) ? h : (const float*)g_agg4;
        const int kloc = (kt & 7) * 16 + acg;

        float4 av = make_float4(0.f, 0.f, 0.f, 0.f);
        const int gr = m0 + arow;
        if (gr < NN) av = *(const float4*)(A + (size_t)gr * DD + kloc);
        As[acg + 0][arow] = av.x;
        As[acg + 1][arow] = av.y;
        As[acg + 2][arow] = av.z;
        As[acg + 3][arow] = av.w;

#pragma unroll
        for (int t = 0; t < 2; ++t) {
            int i = tid + t * 256;
            int r = i >> 5;
            int c = (i & 31) << 2;
            *(float4*)&Ws[r][c] = *(const float4*)(w + (size_t)(kt * 16 + r) * DD + c);
        }
        __syncthreads();

#pragma unroll
        for (int kk = 0; kk < 16; ++kk) {
            float a[8];
#pragma unroll
            for (int i = 0; i < 8; ++i) a[i] = As[kk][ty * 8 + i];
            float4 wv = *(const float4*)&Ws[kk][tx * 4];
#pragma unroll
            for (int i = 0; i < 8; ++i) {
                acc[i][0] = fmaf(a[i], wv.x, acc[i][0]);
                acc[i][1] = fmaf(a[i], wv.y, acc[i][1]);
                acc[i][2] = fmaf(a[i], wv.z, acc[i][2]);
                acc[i][3] = fmaf(a[i], wv.w, acc[i][3]);
            }
        }
        __syncthreads();
    }

    const float4 bias = *(const float4*)(b + tx * 4);
#pragma unroll
    for (int i = 0; i < 8; ++i) {
        int gr = m0 + ty * 8 + i;
        if (gr < NN) {
            float4 v;
            v.x = acc[i][0] + bias.x;
            v.y = acc[i][1] + bias.y;
            v.z = acc[i][2] + bias.z;
            v.w = acc[i][3] + bias.w;
            v.x = v.x > 0.f ? v.x : 0.01f * v.x;
            v.y = v.y > 0.f ? v.y : 0.01f * v.y;
            v.z = v.z > 0.f ? v.z : 0.01f * v.z;
            v.w = v.w > 0.f ? v.w : 0.01f * v.w;
            if (addskip) {
                float4 hv = *(const float4*)(h + (size_t)gr * DD + tx * 4);
                v.x += hv.x; v.y += hv.y; v.z += hv.z; v.w += hv.w;
            }
            *(float4*)(out + (size_t)gr * DD + tx * 4) = v;
        }
    }
}

// ---------------- global pool ----------------
__global__ void k_init_xg() {
    unsigned int i = blockIdx.x * blockDim.x + threadIdx.x;
    if (i < NG * DD) ((unsigned int*)g_xg)[i] = NEG_INF_BITS;
}

__device__ __forceinline__ int lower_bound_b(const int* b32, int n, int v) {
    int lo = 0, hi = n;
    while (lo < hi) {
        int mid = (lo + hi) >> 1;
        if (idx_at(b32, mid) < v) lo = mid + 1;
        else hi = mid;
    }
    return lo;
}

__global__ void k_segmax(const float* __restrict__ h, const int* __restrict__ batch32) {
    const int g = blockIdx.x;
    const int chunk = blockIdx.y;
    const int d = threadIdx.x;
    int start = lower_bound_b(batch32, NN, g);
    int end = lower_bound_b(batch32, NN, g + 1);
    int len = end - start;
    if (len <= 0) return;
    int per = (len + gridDim.y - 1) / gridDim.y;
    int s = start + chunk * per;
    int e = s + per;
    if (e > end) e = end;
    if (s >= e) return;
    float m = __uint_as_float(NEG_INF_BITS);
    for (int r = s; r < e; ++r) m = fmaxf(m, h[(size_t)r * DD + d]);
    atomicMaxF(&g_xg[g * DD + d], m);
}

__global__ void k_combine(float* __restrict__ dout, const float* __restrict__ wg,
                          const float* __restrict__ bg, int out_size) {
    const int g = blockIdx.x;
    const int n = threadIdx.x;
    float acc = bg[n];
    for (int k = 0; k < DD; ++k) {
        float xv = fixneg(g_xg[g * DD + k]);
        acc = fmaf(xv, wg[(size_t)k * DD + n], acc);
    }
    acc = acc > 0.f ? acc : 0.01f * acc;
    long long oi = (long long)NN * DD + g * DD + n;
    if (oi < (long long)out_size) dout[oi] = acc;
}

// ---------------- launch ----------------
extern "C" void kernel_launch(void* const* d_in, const int* in_sizes, int n_in,
                              void* d_out, int out_size) {
    const float* x = (const float*)d_in[0];
    const int* ei32 = (const int*)d_in[1];
    const int* batch32 = (const int*)d_in[2];
    const int wb = n_in - 10;  // w0,b0,w1,b1,w2,b2,w3,b3,wg,bg
    float* dout = (float*)d_out;

    k_detect<<<1, 1>>>(ei32);

    // CSR build (edges constant within a launch)
    k_zero_deg<<<(NN + 255) / 256, 256>>>();
    k_count<<<(NE + 255) / 256, 256>>>(ei32);
    k_scan<<<1, 1024>>>();
    k_fill<<<(NE + 255) / 256, 256>>>(ei32);

    int insel = 0;
    for (int s = 0; s < 4; ++s) {
        int outsel = (s == 3) ? 3 : ((s % 2 == 0) ? 1 : 2);
        k_agg<<<(NN * 32 + 255) / 256, 256>>>(insel, x, dout);
        k_gemm<<<(NN + 63) / 64, 256>>>(insel, outsel, x, dout,
                                        (const float*)d_in[wb + 2 * s],
                                        (const float*)d_in[wb + 2 * s + 1],
                                        s > 0 ? 1 : 0);
        insel = outsel;
    }

    k_init_xg<<<8, 256>>>();
    dim3 gsg(NG, 32);
    k_segmax<<<gsg, 128>>>(dout, batch32);
    k_combine<<<NG, 128>>>(dout, (const float*)d_in[wb + 8], (const float*)d_in[wb + 9], out_size);
}